// round 2
// baseline (speedup 1.0000x reference)
#include <cuda_runtime.h>
#include <cuda_bf16.h>
#include <math.h>

// Problem constants
#define Bn 32
#define Tn 2048
#define Dn 512
#define ZB 32            // number of MVN draws (batch_size)
#define SPLIT 32         // split-K = one batch per K-chunk (Tn each)
#define SEG 8            // T-segments for mean reduction

// ---------------- scratch (static device memory; no runtime allocs) --------
__device__ float g_pmean[SEG][Bn][Dn];        // partial T-sums
__device__ float g_bmean[Bn][Dn];             // per-batch mean over T
__device__ float g_gmean[Dn];                 // global mean
__device__ float g_Gpart[SPLIT][Dn * Dn];     // split-K Gram partials (32 MB)
__device__ float g_C[Dn * Dn];                // covariance -> Cholesky in-place (lower)

// ---------------- 1) per-batch partial means --------------------------------
__global__ void mean_partial(const float* __restrict__ x) {
    int b   = blockIdx.y;
    int seg = blockIdx.z;
    int d   = blockIdx.x * 128 + threadIdx.x;
    const float* p = x + ((size_t)b * Tn + (size_t)seg * (Tn / SEG)) * Dn + d;
    float s = 0.f;
#pragma unroll 8
    for (int t = 0; t < Tn / SEG; t++) s += p[(size_t)t * Dn];
    g_pmean[seg][b][d] = s;
}

__global__ void mean_final() {
    int idx = blockIdx.x * 256 + threadIdx.x;   // over 32*512
    if (idx >= Bn * Dn) return;
    int b = idx / Dn, d = idx % Dn;
    float s = 0.f;
#pragma unroll
    for (int g = 0; g < SEG; g++) s += g_pmean[g][b][d];
    g_bmean[b][d] = s * (1.0f / (float)Tn);
}

__global__ void gmean_kernel() {
    int d = threadIdx.x;   // 512 threads
    float s = 0.f;
#pragma unroll
    for (int b = 0; b < Bn; b++) s += g_bmean[b][d];
    g_gmean[d] = s * (1.0f / (float)Bn);
}

// ---------------- 2) Gram matrix: G = sum_{b,t} xc xc^T ---------------------
// grid (8, 8, 32): tile (bx*64, by*64), K-chunk = batch bz (2048 rows).
// Only lower tiles (by <= bx) computed. 256 threads, 4x4 micro-tile, KB=16.
__global__ void __launch_bounds__(256) gram_kernel(const float* __restrict__ x) {
    if (blockIdx.y > blockIdx.x) return;     // symmetry: lower tiles only
    int bz    = blockIdx.z;                  // batch index == K-chunk
    int dtile = blockIdx.x * 64;
    int etile = blockIdx.y * 64;

    __shared__ __align__(16) float As[16][64];
    __shared__ __align__(16) float Bs[16][64];
    __shared__ float mbd[64], mbe[64];

    int tid = threadIdx.x;
    if (tid < 64)       mbd[tid]      = g_bmean[bz][dtile + tid];
    else if (tid < 128) mbe[tid - 64] = g_bmean[bz][etile + tid - 64];
    __syncthreads();

    int tx = tid & 15;          // 0..15 -> d sub-block
    int ty = tid >> 4;          // 0..15 -> e sub-block
    int kl = tid >> 4;          // load row  0..15
    int d4 = (tid & 15) << 2;   // load col*4

    const float* xb = x + (size_t)bz * Tn * Dn;
    float c[4][4] = {};

    for (int kk = 0; kk < Tn; kk += 16) {
        int t = kk + kl;
        float4 va = *(const float4*)(xb + (size_t)t * Dn + dtile + d4);
        float4 vb = *(const float4*)(xb + (size_t)t * Dn + etile + d4);
        va.x -= mbd[d4]; va.y -= mbd[d4 + 1]; va.z -= mbd[d4 + 2]; va.w -= mbd[d4 + 3];
        vb.x -= mbe[d4]; vb.y -= mbe[d4 + 1]; vb.z -= mbe[d4 + 2]; vb.w -= mbe[d4 + 3];
        *(float4*)&As[kl][d4] = va;
        *(float4*)&Bs[kl][d4] = vb;
        __syncthreads();

#pragma unroll
        for (int k = 0; k < 16; k++) {
            float4 a = *(const float4*)&As[k][tx * 4];
            float4 b = *(const float4*)&Bs[k][ty * 4];
            float av[4] = {a.x, a.y, a.z, a.w};
            float bv[4] = {b.x, b.y, b.z, b.w};
#pragma unroll
            for (int i = 0; i < 4; i++)
#pragma unroll
                for (int j = 0; j < 4; j++)
                    c[i][j] += av[i] * bv[j];
        }
        __syncthreads();
    }

    float* gp = g_Gpart[bz];
#pragma unroll
    for (int i = 0; i < 4; i++)
#pragma unroll
        for (int j = 0; j < 4; j++)
            gp[(size_t)(dtile + tx * 4 + i) * Dn + etile + ty * 4 + j] = c[i][j];
}

// reduce split-K partials -> covariance (write both triangles)
__global__ void gram_reduce() {
    int idx = blockIdx.x * 256 + threadIdx.x;   // over 512*512
    int d = idx / Dn, e = idx % Dn;
    if (e > d) return;                           // only lower computed in partials
    float s = 0.f;
#pragma unroll
    for (int g = 0; g < SPLIT; g++) s += g_Gpart[g][(size_t)d * Dn + e];
    s *= (1.0f / ((float)(Tn - 1) * (float)Bn));
    g_C[(size_t)d * Dn + e] = s;
    g_C[(size_t)e * Dn + d] = s;
}

// ---------------- 3) blocked Cholesky (panel width 32) ----------------------
// One block: factor 32x32 diagonal block + TRSM the panel below it.
__global__ void __launch_bounds__(512) chol_panel(int j0) {
    __shared__ float s[32][33];
    int tid = threadIdx.x;

    for (int e = tid; e < 1024; e += 512)
        s[e >> 5][e & 31] = g_C[(size_t)(j0 + (e >> 5)) * Dn + j0 + (e & 31)];
    __syncthreads();

    for (int j = 0; j < 32; j++) {
        if (tid == 0) s[j][j] = sqrtf(s[j][j]);
        __syncthreads();
        if (tid > j && tid < 32) s[tid][j] /= s[j][j];
        __syncthreads();
        int n = 31 - j;
        for (int idx = tid; idx < n * n; idx += 512) {
            int i = j + 1 + idx / n;
            int k = j + 1 + idx % n;
            if (k <= i) s[i][k] -= s[i][j] * s[k][j];
        }
        __syncthreads();
    }

    // write back diagonal block (lower part)
    for (int e = tid; e < 1024; e += 512) {
        int i = e >> 5, k = e & 31;
        if (k <= i) g_C[(size_t)(j0 + i) * Dn + j0 + k] = s[i][k];
    }

    // TRSM: rows below the diagonal block (one row per thread)
    int i = j0 + 32 + tid;
    if (i < Dn) {
        float a[32];
#pragma unroll
        for (int j = 0; j < 32; j++) a[j] = g_C[(size_t)i * Dn + j0 + j];
#pragma unroll
        for (int j = 0; j < 32; j++) {
            float v = a[j];
            for (int k = 0; k < j; k++) v -= a[k] * s[j][k];
            a[j] = v / s[j][j];
        }
#pragma unroll
        for (int j = 0; j < 32; j++) g_C[(size_t)i * Dn + j0 + j] = a[j];
    }
}

// trailing SYRK update: C[i][k] -= sum_j P[i][j]*P[k][j], lower triangle only
__global__ void __launch_bounds__(1024) chol_syrk(int j0) {
    int r0 = j0 + 32;
    int i0 = r0 + blockIdx.x * 32;
    int k0 = r0 + blockIdx.y * 32;
    if (k0 > i0) return;

    __shared__ float Pi[32][33], Pk[32][33];
    int tid = threadIdx.x;
    int li = tid >> 5, lk = tid & 31;

    Pi[li][lk] = g_C[(size_t)(i0 + li) * Dn + j0 + lk];
    Pk[li][lk] = g_C[(size_t)(k0 + li) * Dn + j0 + lk];
    __syncthreads();

    int gi = i0 + li, gk = k0 + lk;
    if (gk <= gi) {
        float acc = 0.f;
#pragma unroll
        for (int j = 0; j < 32; j++) acc += Pi[li][j] * Pk[lk][j];
        g_C[(size_t)gi * Dn + gk] -= acc;
    }
}

// ---------------- 4) output: out[s][d] = gmean[d] + sum_{e<=d} z[s][e]*L[d][e]
__global__ void __launch_bounds__(512) out_kernel(const float* __restrict__ z,
                                                 float* __restrict__ out) {
    int sidx = blockIdx.x;      // 0..31
    int d    = threadIdx.x;     // 0..511
    __shared__ float zs[Dn];
    zs[d] = z[(size_t)sidx * Dn + d];
    __syncthreads();
    float acc = g_gmean[d];
    const float* Crow = &g_C[(size_t)d * Dn];
    for (int e = 0; e <= d; e++) acc += zs[e] * Crow[e];
    out[(size_t)sidx * Dn + d] = acc;
}

// ---------------- launch ----------------------------------------------------
extern "C" void kernel_launch(void* const* d_in, const int* in_sizes, int n_in,
                              void* d_out, int out_size) {
    // identify inputs by size (x: 33554432 elems, z: 16384 elems)
    const float* x = (const float*)d_in[0];
    const float* z = (const float*)d_in[1];
    if (in_sizes[0] != Bn * Tn * Dn) { x = (const float*)d_in[1]; z = (const float*)d_in[0]; }
    float* out = (float*)d_out;

    mean_partial<<<dim3(4, Bn, SEG), 128>>>(x);
    mean_final<<<(Bn * Dn) / 256, 256>>>();
    gmean_kernel<<<1, Dn>>>();

    gram_kernel<<<dim3(8, 8, SPLIT), 256>>>(x);
    gram_reduce<<<(Dn * Dn) / 256, 256>>>();

    for (int p = 0; p < 16; p++) {
        chol_panel<<<1, 512>>>(p * 32);
        int nt = 15 - p;   // trailing tiles of 32
        if (nt > 0) chol_syrk<<<dim3(nt, nt), 1024>>>(p * 32);
    }

    out_kernel<<<ZB, Dn>>>(z, out);
}